// round 1
// baseline (speedup 1.0000x reference)
#include <cuda_runtime.h>

#define BB 4096
#define TT 2048
#define II 4
#define HH 3

#define LOG2E_F 1.4426950408889634f

__device__ __forceinline__ float ex2f(float x) {
    float y; asm("ex2.approx.f32 %0, %1;" : "=f"(y) : "f"(x)); return y;
}
__device__ __forceinline__ float rcpf(float x) {
    float y; asm("rcp.approx.f32 %0, %1;" : "=f"(y) : "f"(x)); return y;
}

// 4 lanes per batch element. Lane sub=0,1,2 each own one hidden unit
// (compute its i,f,g,o gates, c, h); lane sub=3 duplicates unit 2 so the
// 4-lane group stays converged for the shfl-based h broadcast.
// Weights pre-scaled by -log2(e) (sigmoid rows) / +2*log2(e) (tanh row) so
// ex2.approx directly gives e^{-z} / e^{2z}. c kept in 2*log2(e)-scaled form.
__global__ void __launch_bounds__(128, 1)
lstm_seq_kernel(const float* __restrict__ x,
                const float* __restrict__ Wih,
                const float* __restrict__ Whh,
                const float* __restrict__ bih,
                const float* __restrict__ bhh,
                const int*   __restrict__ lenw,
                float* __restrict__ out)
{
    const int lane = threadIdx.x & 31;
    const int sub  = threadIdx.x & 3;
    const int grp  = threadIdx.x >> 2;            // 0..31 within block
    const int b    = blockIdx.x * 32 + grp;       // batch index (exact: 128*32=4096)
    const int base = lane & ~3;                   // group base lane
    const unsigned gmask = 0xFu << base;

    const int unit = (sub < 3) ? sub : 2;

    // length dtype sniff: lengths are >=1, so int32 interp of element 1 being 0
    // means we are looking at the high word of an int64 array.
    const bool is64 = (lenw[1] == 0);
    int len = is64 ? lenw[2 * b] : lenw[b];
    if (len < 0) len = 0;
    if (len > TT) len = TT;

    const int ri = unit, rf = 3 + unit, rg = 6 + unit, ro = 9 + unit;
    const float SI = -LOG2E_F;        // sigmoid pre-scale
    const float SG = 2.0f * LOG2E_F;  // tanh pre-scale

    float wxi[II], wxf[II], wxg[II], wxo[II];
    #pragma unroll
    for (int k = 0; k < II; k++) {
        wxi[k] = SI * Wih[ri * II + k];
        wxf[k] = SI * Wih[rf * II + k];
        wxg[k] = SG * Wih[rg * II + k];
        wxo[k] = SI * Wih[ro * II + k];
    }
    float whi[HH], whf[HH], whg[HH], who[HH];
    #pragma unroll
    for (int k = 0; k < HH; k++) {
        whi[k] = SI * Whh[ri * HH + k];
        whf[k] = SI * Whh[rf * HH + k];
        whg[k] = SG * Whh[rg * HH + k];
        who[k] = SI * Whh[ro * HH + k];
    }
    const float bi = SI * (bih[ri] + bhh[ri]);
    const float bf = SI * (bih[rf] + bhh[rf]);
    const float bg = SG * (bih[rg] + bhh[rg]);
    const float bo = SI * (bih[ro] + bhh[ro]);

    float h0 = 0.f, h1 = 0.f, h2 = 0.f;
    float cs = 0.f;  // 2*log2e * c

    const float4* __restrict__ xr = (const float4*)(x + (size_t)b * TT * II);
    float* __restrict__ orow = out + (size_t)b * TT * HH;

    // 8-deep register prefetch ring (prefetch distance ~1000 cyc > DRAM lat)
    float4 buf[8];
    #pragma unroll
    for (int p = 0; p < 8; p++) buf[p] = __ldg(&xr[p]);

    auto STEP = [&](float4 xv, int t) {
        // input projection (independent of recurrence)
        float ai = bi, af = bf, ag = bg, ao = bo;
        ai = fmaf(xv.x, wxi[0], ai); ai = fmaf(xv.y, wxi[1], ai);
        ai = fmaf(xv.z, wxi[2], ai); ai = fmaf(xv.w, wxi[3], ai);
        af = fmaf(xv.x, wxf[0], af); af = fmaf(xv.y, wxf[1], af);
        af = fmaf(xv.z, wxf[2], af); af = fmaf(xv.w, wxf[3], af);
        ag = fmaf(xv.x, wxg[0], ag); ag = fmaf(xv.y, wxg[1], ag);
        ag = fmaf(xv.z, wxg[2], ag); ag = fmaf(xv.w, wxg[3], ag);
        ao = fmaf(xv.x, wxo[0], ao); ao = fmaf(xv.y, wxo[1], ao);
        ao = fmaf(xv.z, wxo[2], ao); ao = fmaf(xv.w, wxo[3], ao);
        // recurrent projection (critical path starts here)
        ai = fmaf(h0, whi[0], ai); ai = fmaf(h1, whi[1], ai); ai = fmaf(h2, whi[2], ai);
        af = fmaf(h0, whf[0], af); af = fmaf(h1, whf[1], af); af = fmaf(h2, whf[2], af);
        ag = fmaf(h0, whg[0], ag); ag = fmaf(h1, whg[1], ag); ag = fmaf(h2, whg[2], ag);
        ao = fmaf(h0, who[0], ao); ao = fmaf(h1, who[1], ao); ao = fmaf(h2, who[2], ao);

        const float ei = ex2f(ai);           // e^{-zi}
        const float ef = ex2f(af);           // e^{-zf}
        const float eg = ex2f(ag);           // e^{2*zg}
        const float eo = ex2f(ao);           // e^{-zo}
        const float si  = rcpf(1.f + ei);    // sigmoid(zi)
        const float sf  = rcpf(1.f + ef);    // sigmoid(zf)
        const float rgg = rcpf(1.f + eg);    // (1+e^{2zg})^-1 ; tanh = 1-2*rgg
        const float so  = rcpf(1.f + eo);    // sigmoid(zo)

        const float q    = (2.0f * LOG2E_F) * si;   // scaled i
        const float m2r  = -2.0f * rgg;
        const float igs  = fmaf(m2r, q, q);         // 2log2e * i * tanh(zg)
        cs = fmaf(sf, cs, igs);                     // scaled c update

        const float ec   = ex2f(cs);                // e^{2c}
        const float rc   = rcpf(1.f + ec);
        const float m2so = -2.0f * so;
        const float hn   = fmaf(m2so, rc, so);      // o * tanh(c)

        h0 = __shfl_sync(gmask, hn, base + 0);
        h1 = __shfl_sync(gmask, hn, base + 1);
        h2 = __shfl_sync(gmask, hn, base + 2);

        if (sub < 3) orow[t * HH + sub] = hn;
    };

    int t = 0;
    const int nfull = len & ~7;
    for (; t < nfull; t += 8) {
        #pragma unroll
        for (int u = 0; u < 8; u++) {
            float4 xv = buf[u];
            const int nt = t + 8 + u;
            if (nt < TT) buf[u] = __ldg(&xr[nt]);
            STEP(xv, t + u);
        }
    }
    {
        const int rem = len - nfull;  // 0..7, uniform within the 4-lane group
        #pragma unroll
        for (int u = 0; u < 8; u++) {
            if (u < rem) STEP(buf[u], nfull + u);
        }
    }

    // zero the masked tail (d_out is poisoned)
    for (int i = len * HH + sub; i < TT * HH; i += 4) orow[i] = 0.0f;
}

extern "C" void kernel_launch(void* const* d_in, const int* in_sizes, int n_in,
                              void* d_out, int out_size)
{
    const float* x   = (const float*)d_in[0];
    const float* Wih = (const float*)d_in[1];
    const float* Whh = (const float*)d_in[2];
    const float* bih = (const float*)d_in[3];
    const float* bhh = (const float*)d_in[4];
    const int*   len = (const int*)  d_in[5];
    float* out = (float*)d_out;
    (void)in_sizes; (void)n_in; (void)out_size;

    // 4096 batches * 4 lanes = 16384 threads = 128 blocks x 128
    lstm_seq_kernel<<<128, 128>>>(x, Wih, Whh, bih, bhh, len, out);
}